// round 13
// baseline (speedup 1.0000x reference)
#include <cuda_runtime.h>

// out[b, n] = sum_e c[b, n, e] * s[b, e]
//   B=32, N=8192, E=256 (fp32).  HBM-bound: 256 MB streamed once.
//
// R12 -> R13: persistent grid-stride kernel.
//   grid = 1216 (152 SMs x 8 CTAs, 32 regs -> full residency), each warp
//   loops over 2-row work units with a grid-wide stride (~13.5 iters/warp,
//   balance +-1 iter). Removes wave quantization AND 16K-block launch churn.
//   Per-unit path unchanged: MLP=4 (4x LDG.128 streaming), register weights
//   (reloaded per iter via __ldg, L1 hit), butterfly reduce, float2 store.

static constexpr int B = 32;
static constexpr int N = 8192;              // rows per batch
static constexpr int E4 = 64;               // 256 floats = 64 float4 per row
static constexpr int WARPS_PER_BLOCK = 8;
static constexpr int THREADS = WARPS_PER_BLOCK * 32;        // 256
static constexpr int ROWS_PER_UNIT = 2;
static constexpr int TOTAL_ROWS = B * N;                    // 262144
static constexpr int TOTAL_UNITS = TOTAL_ROWS / ROWS_PER_UNIT;  // 131072
static constexpr int NUM_BLOCKS = 152 * 8;                  // 1216 (capacity)
static constexpr int TOTAL_WARPS = NUM_BLOCKS * WARPS_PER_BLOCK;  // 9728

__device__ __forceinline__ float dot8(float4 a0, float4 a1, float4 w0, float4 w1)
{
    float s = a0.x * w0.x;
    s = fmaf(a0.y, w0.y, s);
    s = fmaf(a0.z, w0.z, s);
    s = fmaf(a0.w, w0.w, s);
    s = fmaf(a1.x, w1.x, s);
    s = fmaf(a1.y, w1.y, s);
    s = fmaf(a1.z, w1.z, s);
    s = fmaf(a1.w, w1.w, s);
    return s;
}

__device__ __forceinline__ float warp_reduce(float v)
{
    #pragma unroll
    for (int off = 16; off > 0; off >>= 1)
        v += __shfl_xor_sync(0xFFFFFFFFu, v, off);
    return v;
}

__global__ __launch_bounds__(THREADS)
void css_dot_kernel(const float4* __restrict__ c,
                    const float4* __restrict__ s,
                    float* __restrict__ out)
{
    const int warp = threadIdx.x >> 5;
    const int lane = threadIdx.x & 31;
    const int gw   = blockIdx.x * WARPS_PER_BLOCK + warp;   // global warp id

    for (int unit = gw; unit < TOTAL_UNITS; unit += TOTAL_WARPS) {
        const int row0 = unit * ROWS_PER_UNIT;              // global row
        const int b    = unit >> 12;                        // row0 / N

        // Weights for this unit's batch (L1/const-cache hit after first touch).
        const float4 w0 = __ldg(s + (size_t)b * E4 + lane);
        const float4 w1 = __ldg(s + (size_t)b * E4 + lane + 32);

        const float4* __restrict__ rA = c + (size_t)row0 * E4;
        const float4* __restrict__ rB = rA + E4;

        // 4 independent 128-bit streaming loads per lane (MLP=4).
        float4 a0 = __ldcs(rA + lane);
        float4 a1 = __ldcs(rA + lane + 32);
        float4 b0 = __ldcs(rB + lane);
        float4 b1 = __ldcs(rB + lane + 32);

        float sumA = warp_reduce(dot8(a0, a1, w0, w1));
        float sumB = warp_reduce(dot8(b0, b1, w0, w1));

        if (lane == 0) {
            float2 r; r.x = sumA; r.y = sumB;
            *reinterpret_cast<float2*>(out + row0) = r;
        }
    }
}

extern "C" void kernel_launch(void* const* d_in, const int* in_sizes, int n_in,
                              void* d_out, int out_size)
{
    (void)in_sizes; (void)n_in; (void)out_size;
    const float4* c = (const float4*)d_in[0];
    const float4* s = (const float4*)d_in[1];
    float* out = (float*)d_out;

    css_dot_kernel<<<NUM_BLOCKS, THREADS>>>(c, s, out);
}

// round 14
// speedup vs baseline: 1.0610x; 1.0610x over previous
#include <cuda_runtime.h>

// out[b, n] = sum_e c[b, n, e] * s[b, e]
//   B=32, N=8192, E=256 (fp32).  HBM-bound: 256 MB streamed once.
//
// R13 -> R14: persistent kernel, take 2.
//   R13 failed because the loop grew regs 32->40 -> 6 CTAs/SM (occ 64.6%,
//   DRAM 74%). Fix: __launch_bounds__(256, 8) forces the 32-reg budget for
//   full 8-CTA/SM residency, and the loop body is slimmed (loop-carried
//   pointer increment instead of per-iter address recompute).
//   Per-unit path unchanged from R12: 2 rows/unit, MLP=4 (4x LDG.128
//   streaming), register weights, butterfly reduce, float2 store.

static constexpr int B = 32;
static constexpr int N = 8192;              // rows per batch
static constexpr int E4 = 64;               // 256 floats = 64 float4 per row
static constexpr int WARPS_PER_BLOCK = 8;
static constexpr int THREADS = WARPS_PER_BLOCK * 32;        // 256
static constexpr int ROWS_PER_UNIT = 2;
static constexpr int UNIT_F4 = ROWS_PER_UNIT * E4;          // 128 float4 per unit
static constexpr int TOTAL_ROWS = B * N;                    // 262144
static constexpr int TOTAL_UNITS = TOTAL_ROWS / ROWS_PER_UNIT;  // 131072
static constexpr int NUM_BLOCKS = 152 * 8;                  // 1216 (capacity)
static constexpr int TOTAL_WARPS = NUM_BLOCKS * WARPS_PER_BLOCK;  // 9728
static constexpr int UNITS_PER_BATCH = N / ROWS_PER_UNIT;   // 4096

__device__ __forceinline__ float dot8(float4 a0, float4 a1, float4 w0, float4 w1)
{
    float s = a0.x * w0.x;
    s = fmaf(a0.y, w0.y, s);
    s = fmaf(a0.z, w0.z, s);
    s = fmaf(a0.w, w0.w, s);
    s = fmaf(a1.x, w1.x, s);
    s = fmaf(a1.y, w1.y, s);
    s = fmaf(a1.z, w1.z, s);
    s = fmaf(a1.w, w1.w, s);
    return s;
}

__device__ __forceinline__ float warp_reduce(float v)
{
    #pragma unroll
    for (int off = 16; off > 0; off >>= 1)
        v += __shfl_xor_sync(0xFFFFFFFFu, v, off);
    return v;
}

__global__ __launch_bounds__(THREADS, 8)
void css_dot_kernel(const float4* __restrict__ c,
                    const float4* __restrict__ s,
                    float* __restrict__ out)
{
    const int warp = threadIdx.x >> 5;
    const int lane = threadIdx.x & 31;
    const int gw   = blockIdx.x * WARPS_PER_BLOCK + warp;   // global warp id

    // Loop-carried pointers: one add per iteration, no address recompute.
    const float4* rA = c + (size_t)gw * UNIT_F4 + lane;
    float*        po = out + (size_t)gw * ROWS_PER_UNIT;

    for (int unit = gw; unit < TOTAL_UNITS;
         unit += TOTAL_WARPS,
         rA   += (size_t)TOTAL_WARPS * UNIT_F4,
         po   += (size_t)TOTAL_WARPS * ROWS_PER_UNIT)
    {
        // 4 independent 128-bit streaming loads (MLP=4): issue first.
        float4 a0 = __ldcs(rA);
        float4 a1 = __ldcs(rA + 32);
        float4 b0 = __ldcs(rA + 64);
        float4 b1 = __ldcs(rA + 96);

        // Weights for this unit's batch (L1-hot, overlapped with the
        // streaming loads above).
        const int bidx = unit / UNITS_PER_BATCH;
        const float4* sw = s + bidx * E4 + lane;
        float4 w0 = sw[0];
        float4 w1 = sw[32];

        float sumA = warp_reduce(dot8(a0, a1, w0, w1));
        float sumB = warp_reduce(dot8(b0, b1, w0, w1));

        if (lane == 0) {
            float2 r; r.x = sumA; r.y = sumB;
            *reinterpret_cast<float2*>(po) = r;
        }
    }
}

extern "C" void kernel_launch(void* const* d_in, const int* in_sizes, int n_in,
                              void* d_out, int out_size)
{
    (void)in_sizes; (void)n_in; (void)out_size;
    const float4* c = (const float4*)d_in[0];
    const float4* s = (const float4*)d_in[1];
    float* out = (float*)d_out;

    css_dot_kernel<<<NUM_BLOCKS, THREADS>>>(c, s, out);
}

// round 15
// speedup vs baseline: 1.1535x; 1.0872x over previous
#include <cuda_runtime.h>

// out[b, n] = sum_e c[b, n, e] * s[b, e]
//   B=32, N=8192, E=256 (fp32).  HBM-bound: 256 MB streamed once.
//
// R14 -> R15: back to block-churn (persistence lost twice: reg-starved
// prefetch makes per-warp load duty drop). Minimal-warp variant of R12:
//   ROWS_PER_WARP 2 -> 1, grid 32768. MLP_p1 = 2 zeroes the cross-CTA
//   L1tex-queue spread term (oe*MLP_p1 = 16 = Q_th), trading per-warp MLP
//   (still ample in aggregate: 64 warps/SM x 2 LDG.128) for a tighter
//   finish distribution. No smem, no sync, no loop: 2 streaming LDG.128,
//   2 L1-hot weight loads, 8 FMA, 1 butterfly reduce, 1 scalar store.

static constexpr int B = 32;
static constexpr int N = 8192;              // rows per batch
static constexpr int E4 = 64;               // 256 floats = 64 float4 per row
static constexpr int WARPS_PER_BLOCK = 8;
static constexpr int THREADS = WARPS_PER_BLOCK * 32;        // 256
static constexpr int TOTAL_ROWS = B * N;                    // 262144
static constexpr int NUM_BLOCKS = TOTAL_ROWS / WARPS_PER_BLOCK;  // 32768

__device__ __forceinline__ float dot8(float4 a0, float4 a1, float4 w0, float4 w1)
{
    float s = a0.x * w0.x;
    s = fmaf(a0.y, w0.y, s);
    s = fmaf(a0.z, w0.z, s);
    s = fmaf(a0.w, w0.w, s);
    s = fmaf(a1.x, w1.x, s);
    s = fmaf(a1.y, w1.y, s);
    s = fmaf(a1.z, w1.z, s);
    s = fmaf(a1.w, w1.w, s);
    return s;
}

__device__ __forceinline__ float warp_reduce(float v)
{
    #pragma unroll
    for (int off = 16; off > 0; off >>= 1)
        v += __shfl_xor_sync(0xFFFFFFFFu, v, off);
    return v;
}

__global__ __launch_bounds__(THREADS)
void css_dot_kernel(const float4* __restrict__ c,
                    const float4* __restrict__ s,
                    float* __restrict__ out)
{
    const int warp = threadIdx.x >> 5;
    const int lane = threadIdx.x & 31;
    const int row  = blockIdx.x * WARPS_PER_BLOCK + warp;   // one row per warp
    const int b    = row >> 13;                             // row / N

    const float4* __restrict__ rp = c + (size_t)row * E4;

    // Two independent 128-bit streaming loads per lane (MLP_p1 = 2).
    float4 a0 = __ldcs(rp + lane);
    float4 a1 = __ldcs(rp + lane + 32);

    // Weights for this batch (L1-hot broadcast across the 256 warps/batch).
    const float4* __restrict__ sw = s + b * E4 + lane;
    float4 w0 = sw[0];
    float4 w1 = sw[32];

    float sum = warp_reduce(dot8(a0, a1, w0, w1));

    if (lane == 0)
        out[row] = sum;
}

extern "C" void kernel_launch(void* const* d_in, const int* in_sizes, int n_in,
                              void* d_out, int out_size)
{
    (void)in_sizes; (void)n_in; (void)out_size;
    const float4* c = (const float4*)d_in[0];
    const float4* s = (const float4*)d_in[1];
    float* out = (float*)d_out;

    css_dot_kernel<<<NUM_BLOCKS, THREADS>>>(c, s, out);
}